// round 16
// baseline (speedup 1.0000x reference)
#include <cuda_runtime.h>
#include <cstdint>

#define BATCH 4
#define CHAN  128
#define CF    64
#define HW    9216
#define MH    2304
#define NC    (HW - MH)          // 6912
#define CTILE 128
#define RTILE 128
#define NTILES (NC / CTILE)      // 54
#define NROWB  (MH / RTILE)      // 18
#define TILE_PLANE 8192          // floats per (tile, plane) image
#define TILE_FLOATS (2 * TILE_PLANE)
#define NTHREADS 512

// ---------------- scratch (__device__ globals) ------------------------------
__device__ float g_rn_f [BATCH * HW];
__device__ int   g_colidx[2][BATCH][NC];
__device__ float g_Bt [2][BATCH][NTILES][2][TILE_PLANE]; // fragment-packed hi/lo (col-scaled)
__device__ float g_max[2][BATCH * MH];
__device__ int   g_arg[2][BATCH * MH];
__device__ int   g_colflag[2][BATCH * HW];
__device__ unsigned char g_selmap[BATCH * HW];
__device__ float g_S[BATCH][2][CF];

// ---------------- helpers ---------------------------------------------------
__device__ __forceinline__ float tf32_rn(float a)
{
    uint32_t u;
    asm("cvt.rna.tf32.f32 %0, %1;" : "=r"(u) : "f"(a));
    return __uint_as_float(u);
}
__device__ __forceinline__ void cp_async16(uint32_t smem_addr, const void* gmem_src)
{
    asm volatile("cp.async.cg.shared.global [%0], [%1], 16;" :: "r"(smem_addr), "l"(gmem_src));
}
__device__ __forceinline__ void cp_async_commit() { asm volatile("cp.async.commit_group;"); }
__device__ __forceinline__ void cp_async_wait0()  { asm volatile("cp.async.wait_group 0;"); }
__device__ __forceinline__ uint32_t smem_u32(const void* p)
{
    uint32_t a;
    asm("{ .reg .u64 t; cvta.to.shared.u64 t, %1; cvt.u32.u64 %0, t; }" : "=r"(a) : "l"(p));
    return a;
}
// m16n8k8 tf32 mma, D accumulate in place
__device__ __forceinline__ void mma8(float* d, const uint4& a, uint32_t b0, uint32_t b1)
{
    asm volatile(
        "mma.sync.aligned.m16n8k8.row.col.f32.tf32.tf32.f32 "
        "{%0,%1,%2,%3}, {%4,%5,%6,%7}, {%8,%9}, {%0,%1,%2,%3};"
        : "+f"(d[0]), "+f"(d[1]), "+f"(d[2]), "+f"(d[3])
        : "r"(a.x), "r"(a.y), "r"(a.z), "r"(a.w), "r"(b0), "r"(b1));
}

// ---------------- kernel A: former-pixel inverse norms -----------------------
__global__ void norms_kernel(const float* __restrict__ x)
{
    int j = blockIdx.x * 256 + threadIdx.x;
    int b = blockIdx.y;
    if (j >= HW) return;
    const float* fx = x + (size_t)b * CHAN * HW;
    float nf = 0.f;
#pragma unroll 8
    for (int c = 0; c < CF; c++) {
        float a = fx[(size_t)c * HW + j];
        nf += a * a;
    }
    g_rn_f[b * HW + j] = 1.0f / sqrtf(nf);
}

// ---------------- kernel A2: compaction + scratch zeroing (fused) ------------
__global__ void compact_kernel(const int* __restrict__ flag,
                               const int* __restrict__ flagf)
{
    const int b = blockIdx.x, br = blockIdx.y;
    const int* fl = (br ? flagf : flag) + b * HW;
    __shared__ int cnt[1024];
    const int t = threadIdx.x;
    const int PER = HW / 1024;             // 9
    const int base = t * PER;

    // fused zeroing (was zero_kernel): each block owns its (br,b) slices
    {
        int* cf = g_colflag[br] + b * HW;
#pragma unroll
        for (int i = 0; i < PER; i++) cf[base + i] = 0;
        if (br == 0) {
            unsigned char* sm = g_selmap + b * HW;
#pragma unroll
            for (int i = 0; i < PER; i++) sm[base + i] = 0;
        }
    }

    int c = 0;
#pragma unroll
    for (int i = 0; i < PER; i++) c += (fl[base + i] == 0);
    cnt[t] = c;
    __syncthreads();
    for (int off = 1; off < 1024; off <<= 1) {
        int v = (t >= off) ? cnt[t - off] : 0;
        __syncthreads();
        cnt[t] += v;
        __syncthreads();
    }
    int pos = cnt[t] - c;
#pragma unroll
    for (int i = 0; i < PER; i++) {
        int j = base + i;
        if (fl[j] == 0) g_colidx[br][b][pos++] = j;
    }
}

// ---------------- kernel A3: build fragment-packed split B tile images -------
// Computes column inverse norms in-place (ascending-k order), scales columns,
// tf32-splits, packs fragments.
// Layout per tile per plane: [npair(8)][kstep(8)][lane(32)][4 floats]
//   e=0: B[k][n0]  e=1: B[k+4][n0]  e=2: B[k][n1]  e=3: B[k+4][n1]
//   k = kstep*8 + (lane&3), n0/n1 = npair*16 + {0,8} + (lane>>2)
__global__ void bimage_kernel(const float* __restrict__ x,
                              const float* __restrict__ flip)
{
    __shared__ float raw[64][129];
    __shared__ float rcs[CTILE];
    const int t  = blockIdx.x;
    const int b  = blockIdx.y;
    const int br = blockIdx.z;
    const float* Bmat = br ? (flip + (size_t)b * CF * HW)
                           : (x + (size_t)b * CHAN * HW + (size_t)CF * HW);
    const int* cidx = g_colidx[br][b] + t * CTILE;
    const int tid = threadIdx.x;

    for (int e = tid; e < CTILE * 64; e += 256) {
        int n = e & 127, k = e >> 7;
        raw[k][n] = Bmat[(size_t)k * HW + cidx[n]];
    }
    __syncthreads();

    if (tid < CTILE) {
        float s = 0.f;
#pragma unroll 8
        for (int k = 0; k < 64; k++) {
            float v = raw[k][tid];
            s += v * v;
        }
        rcs[tid] = 1.0f / sqrtf(s);
    }
    __syncthreads();

    float* dst_hi = &g_Bt[br][b][t][0][0];
    float* dst_lo = &g_Bt[br][b][t][1][0];
    for (int l = tid; l < TILE_PLANE; l += 256) {
        int np = l >> 10, ks = (l >> 7) & 7, ln = (l >> 2) & 31, e = l & 3;
        int tg = ln & 3, g = ln >> 2;
        int k = ks * 8 + tg + (e & 1) * 4;
        int n = np * 16 + (e >> 1) * 8 + g;
        float v  = raw[k][n] * rcs[n];
        float hi = tf32_rn(v);
        float lo = tf32_rn(v - hi);
        dst_hi[l] = hi;
        dst_lo[l] = lo;
    }
}

// ---------------- kernel B: scored argmax GEMM via mma.sync tf32 x3 ----------
// 512 thr = 16 warps; block tile 128r x 128c; warp tile 32r x 32c (grid 4x4).
// SINGLE barrier per tile: wait -> sync -> issue prefetch(t+1) -> compute.
// dyn smem: A_pk 64KB + B_pk[2 bufs] 128KB = 192KB
__global__ void __launch_bounds__(NTHREADS, 1)
score_kernel(const float* __restrict__ x,
             const int* __restrict__ p, const int* __restrict__ q)
{
    extern __shared__ __align__(16) char dyn[];
    __shared__ int   rowPix[RTILE];
    __shared__ float rnrow [RTILE];
    __shared__ float redv[RTILE * 16];
    __shared__ int   redj[RTILE * 16];

    const uint32_t sbase = smem_u32(dyn);
    const int rowBlk = blockIdx.x;
    const int b      = blockIdx.y;
    const int br     = blockIdx.z;
    const int tid  = threadIdx.x;
    const int lane = tid & 31;
    const int w    = tid >> 5;
    const int wr   = w & 3, wc = w >> 2;       // warp grid 4 (rows) x 4 (cols)
    const int tg   = lane & 3, g = lane >> 2;

    const int*   idx  = (br ? q : p) + b * MH;
    const float* Amat = x + (size_t)b * CHAN * HW;
    const int*   cidx = g_colidx[br][b];
    const float* Bsrc = &g_Bt[br][b][0][0][0];   // [tile][2][8192]

    if (tid < RTILE) {
        int pix = idx[rowBlk * RTILE + tid];
        rowPix[tid] = pix;
        rnrow [tid] = g_rn_f[b * HW + pix];
    }
    __syncthreads();

    // prologue: async-load B tile 0 (64KB) into buf 0
    {
        const float4* src = (const float4*)Bsrc;
#pragma unroll
        for (int i = 0; i < 8; i++) {
            int l = tid + i * NTHREADS;
            cp_async16(sbase + 65536u + l * 16, src + l);
        }
        cp_async_commit();
    }

    // A pack: gather rows, scale by row inverse norm, tf32 split, fragment layout
    // [plane][mt(8)][ks(8)][lane][4]: e0:(r,k) e1:(r+8,k) e2:(r,k+4) e3:(r+8,k+4)
    {
        float* Af = (float*)dyn;
        for (int l = tid; l < TILE_PLANE; l += NTHREADS) {
            int mt = l >> 10, ks = (l >> 7) & 7, ln = (l >> 2) & 31, e = l & 3;
            int ltg = ln & 3, lg = ln >> 2;
            int r = mt * 16 + lg + (e & 1) * 8;
            int k = ks * 8 + ltg + (e >> 1) * 4;
            float v  = Amat[(size_t)k * HW + rowPix[r]] * rnrow[r];
            float hi = tf32_rn(v);
            Af[l]              = hi;
            Af[TILE_PLANE + l] = tf32_rn(v - hi);
        }
    }

    float best[2][2];  int bestj[2][2];        // [mt][half(row +0/+8)], compact col
#pragma unroll
    for (int i = 0; i < 2; i++)
#pragma unroll
        for (int h = 0; h < 2; h++) { best[i][h] = __int_as_float(0xff800000); bestj[i][h] = 0; }

    const uint4* Apk = (const uint4*)dyn;         // plane stride 2048 uint4
    const int colbase = wc * 32 + tg * 2;         // tile-local compact col of e even

    for (int t = 0; t < NTILES; t++) {
        const int jt = t * CTILE;

        cp_async_wait0();
        __syncthreads();   // tile t visible to all; everyone done reading buf^1

        // prefetch t+1 into the other buffer (safe: barrier above ordered
        // all prior reads of buf^1 before these writes)
        if (t + 1 < NTILES) {
            const float4* src = (const float4*)(Bsrc + (size_t)(t + 1) * TILE_FLOATS);
            uint32_t dst = sbase + 65536u + ((t + 1) & 1) * 65536u;
#pragma unroll
            for (int i = 0; i < 8; i++) {
                int l = tid + i * NTHREADS;
                cp_async16(dst + l * 16, src + l);
            }
            cp_async_commit();
        }

        const uint4* Bpk = (const uint4*)(dyn + 65536 + (t & 1) * 65536);

        float acc[2][4][4];   // [mt][np*2+half][c0..c3]
#pragma unroll
        for (int mt = 0; mt < 2; mt++)
#pragma unroll
            for (int j = 0; j < 4; j++)
#pragma unroll
                for (int e = 0; e < 4; e++) acc[mt][j][e] = 0.f;

#pragma unroll 2
        for (int ks = 0; ks < 8; ks++) {
            uint4 ah[2], al[2], bh[2], bl[2];
#pragma unroll
            for (int mt = 0; mt < 2; mt++) {
                int o = ((wr * 2 + mt) * 8 + ks) * 32 + lane;
                ah[mt] = Apk[o];
                al[mt] = Apk[2048 + o];
            }
#pragma unroll
            for (int np = 0; np < 2; np++) {
                int o = ((wc * 2 + np) * 8 + ks) * 32 + lane;
                bh[np] = Bpk[o];
                bl[np] = Bpk[2048 + o];
            }
            // measured-good grouping: per (mt,np), 6 MMAs (a0 hh/hl/lh, a1 hh/hl/lh)
#pragma unroll
            for (int mt = 0; mt < 2; mt++) {
#pragma unroll
                for (int np = 0; np < 2; np++) {
                    float* a0 = acc[mt][np * 2];
                    float* a1 = acc[mt][np * 2 + 1];
                    mma8(a0, ah[mt], bh[np].x, bh[np].y);   // hi*hi
                    mma8(a0, ah[mt], bl[np].x, bl[np].y);   // hi*lo
                    mma8(a0, al[mt], bh[np].x, bh[np].y);   // lo*hi
                    mma8(a1, ah[mt], bh[np].z, bh[np].w);
                    mma8(a1, ah[mt], bl[np].z, bl[np].w);
                    mma8(a1, al[mt], bh[np].z, bh[np].w);
                }
            }
        }

        // epilogue: tree argmax in compact coords (strict-greater picks right
        // => lower column wins ties; columns ascend left-to-right everywhere)
#pragma unroll
        for (int mt = 0; mt < 2; mt++) {
#pragma unroll
            for (int h = 0; h < 2; h++) {
                float wv[4]; int wcid[4];
#pragma unroll
                for (int jj = 0; jj < 4; jj++) {
                    float v0 = acc[mt][jj][2 * h], v1 = acc[mt][jj][2 * h + 1];
                    bool gg = v1 > v0;
                    wv[jj]   = gg ? v1 : v0;
                    wcid[jj] = colbase + jj * 8 + (gg ? 1 : 0);
                }
                bool g0 = wv[1] > wv[0];
                float x0 = g0 ? wv[1] : wv[0];  int c0 = g0 ? wcid[1] : wcid[0];
                bool g1 = wv[3] > wv[2];
                float x1 = g1 ? wv[3] : wv[2];  int c1 = g1 ? wcid[3] : wcid[2];
                bool g2 = x1 > x0;
                float xt = g2 ? x1 : x0;        int ct = g2 ? c1 : c0;
                if (xt > best[mt][h]) { best[mt][h] = xt; bestj[mt][h] = jt + ct; }
            }
        }
        // no end-of-loop barrier: next iteration's wait+sync provides ordering
    }

    // final reduction: 16 slices per row; tie -> lower compact col (== lower orig col)
    const int slice = wc * 4 + tg;
#pragma unroll
    for (int mt = 0; mt < 2; mt++)
#pragma unroll
        for (int h = 0; h < 2; h++) {
            int r = wr * 32 + mt * 16 + g + h * 8;
            redv[r * 16 + slice] = best[mt][h];
            redj[r * 16 + slice] = bestj[mt][h];
        }
    __syncthreads();
    if (tid < RTILE) {
        float bv = __int_as_float(0xff800000);
        int bj = 0;
#pragma unroll 4
        for (int s = 0; s < 16; s++) {
            float v  = redv[tid * 16 + s];
            int   j2 = redj[tid * 16 + s];
            if (v > bv || (v == bv && j2 < bj)) { bv = v; bj = j2; }
        }
        int gi = b * MH + rowBlk * RTILE + tid;
        g_max[br][gi] = bv;
        g_arg[br][gi] = cidx[bj];      // compact -> original column index
    }
}

// ---------------- epilogue chain ---------------------------------------------
__global__ void scatter_kernel(const int* __restrict__ p)
{
    int t = blockIdx.x * 256 + threadIdx.x;
    if (t >= BATCH * MH) return;
    int b = t / MH;
    g_colflag[0][b * HW + g_arg[0][t]] = 1;
    g_colflag[1][b * HW + g_arg[1][t]] = 1;
    int pix = p[t];
    if (pix != 0)
        g_selmap[b * HW + pix] = (g_max[0][t] >= g_max[1][t]) ? 1 : 2;
}

__global__ void ssum_kernel(const float* __restrict__ x, const float* __restrict__ flip)
{
    int c  = blockIdx.x;
    int b  = blockIdx.y;
    int br = blockIdx.z;
    const float* Bmat = br ? (flip + (size_t)b * CF * HW)
                           : (x + (size_t)b * CHAN * HW + (size_t)CF * HW);
    const int* cfl = g_colflag[br] + b * HW;
    float s = 0.f;
    for (int j = threadIdx.x; j < HW; j += 256)
        if (cfl[j]) s += Bmat[(size_t)c * HW + j];
    __shared__ float red[256];
    red[threadIdx.x] = s;
    __syncthreads();
    for (int off = 128; off > 0; off >>= 1) {
        if (threadIdx.x < off) red[threadIdx.x] += red[threadIdx.x + off];
        __syncthreads();
    }
    if (threadIdx.x == 0) g_S[b][br][c] = red[0];
}

__global__ void out_kernel(const float* __restrict__ x, float* __restrict__ out)
{
    unsigned int idx = blockIdx.x * 256u + threadIdx.x;
    const unsigned int total = BATCH * 192u * HW;
    if (idx >= total) return;
    unsigned int b   = idx / (192u * HW);
    unsigned int rem = idx - b * 192u * HW;
    unsigned int ch  = rem / HW;
    unsigned int j   = rem - ch * HW;
    float v;
    if (ch < CHAN) {
        v = x[(size_t)b * CHAN * HW + rem];
    } else {
        int s = g_selmap[b * HW + j];
        v = s ? g_S[b][s - 1][ch - CHAN] : 0.f;
    }
    out[idx] = v;
}

// ---------------- launch -----------------------------------------------------
extern "C" void kernel_launch(void* const* d_in, const int* in_sizes, int n_in,
                              void* d_out, int out_size)
{
    const float* x     = (const float*)d_in[0];
    const float* flip  = (const float*)d_in[1];
    const int*   flag  = (const int*)d_in[2];
    const int*   flagf = (const int*)d_in[3];
    const int*   p     = (const int*)d_in[4];
    const int*   q     = (const int*)d_in[5];
    float* out = (float*)d_out;

    const int score_smem = 65536 + 2 * 65536;       // A_pk + 2 B buffers = 192 KB
    static bool attr_set = false;
    if (!attr_set) {
        cudaFuncSetAttribute(score_kernel,
                             cudaFuncAttributeMaxDynamicSharedMemorySize, score_smem);
        attr_set = true;
    }

    norms_kernel   <<<dim3(HW / 256, BATCH), 256>>>(x);
    compact_kernel <<<dim3(BATCH, 2), 1024>>>(flag, flagf);
    bimage_kernel  <<<dim3(NTILES, BATCH, 2), 256>>>(x, flip);
    score_kernel   <<<dim3(NROWB, BATCH, 2), NTHREADS, score_smem>>>(x, p, q);
    scatter_kernel <<<(BATCH * MH + 255) / 256, 256>>>(p);
    ssum_kernel    <<<dim3(CF, BATCH, 2), 256>>>(x, flip);
    out_kernel     <<<(BATCH * 192 * HW + 255) / 256, 256>>>(x, out);
}

// round 17
// speedup vs baseline: 1.0095x; 1.0095x over previous
#include <cuda_runtime.h>
#include <cstdint>

#define BATCH 4
#define CHAN  128
#define CF    64
#define HW    9216
#define MH    2304
#define NC    (HW - MH)          // 6912
#define CTILE 128
#define RTILE 128
#define NTILES (NC / CTILE)      // 54
#define NROWB  (MH / RTILE)      // 18
#define TILE_PLANE 8192          // floats per (tile, plane) image
#define TILE_FLOATS (2 * TILE_PLANE)
#define NTHREADS 512

// ---------------- scratch (__device__ globals) ------------------------------
__device__ float g_rn_f [BATCH * HW];
__device__ int   g_colidx[2][BATCH][NC];
__device__ float g_Bt [2][BATCH][NTILES][2][TILE_PLANE]; // fragment-packed hi/lo (col-scaled)
__device__ float g_max[2][BATCH * MH];
__device__ int   g_arg[2][BATCH * MH];
__device__ int   g_colflag[2][BATCH * HW];
__device__ unsigned char g_selmap[BATCH * HW];
__device__ float g_S[BATCH][2][CF];

// ---------------- helpers ---------------------------------------------------
__device__ __forceinline__ float tf32_rn(float a)
{
    uint32_t u;
    asm("cvt.rna.tf32.f32 %0, %1;" : "=r"(u) : "f"(a));
    return __uint_as_float(u);
}
__device__ __forceinline__ void cp_async16(uint32_t smem_addr, const void* gmem_src)
{
    asm volatile("cp.async.cg.shared.global [%0], [%1], 16;" :: "r"(smem_addr), "l"(gmem_src));
}
__device__ __forceinline__ void cp_async_commit() { asm volatile("cp.async.commit_group;"); }
__device__ __forceinline__ void cp_async_wait0()  { asm volatile("cp.async.wait_group 0;"); }
__device__ __forceinline__ uint32_t smem_u32(const void* p)
{
    uint32_t a;
    asm("{ .reg .u64 t; cvta.to.shared.u64 t, %1; cvt.u32.u64 %0, t; }" : "=r"(a) : "l"(p));
    return a;
}
// m16n8k8 tf32 mma, D accumulate in place
__device__ __forceinline__ void mma8(float* d, const uint4& a, uint32_t b0, uint32_t b1)
{
    asm volatile(
        "mma.sync.aligned.m16n8k8.row.col.f32.tf32.tf32.f32 "
        "{%0,%1,%2,%3}, {%4,%5,%6,%7}, {%8,%9}, {%0,%1,%2,%3};"
        : "+f"(d[0]), "+f"(d[1]), "+f"(d[2]), "+f"(d[3])
        : "r"(a.x), "r"(a.y), "r"(a.z), "r"(a.w), "r"(b0), "r"(b1));
}

// ---------------- kernel A2: compaction + scratch zeroing (fused) ------------
__global__ void compact_kernel(const int* __restrict__ flag,
                               const int* __restrict__ flagf)
{
    const int b = blockIdx.x, br = blockIdx.y;
    const int* fl = (br ? flagf : flag) + b * HW;
    __shared__ int cnt[1024];
    const int t = threadIdx.x;
    const int PER = HW / 1024;             // 9
    const int base = t * PER;

    // fused zeroing: each block owns its (br,b) slices
    {
        int* cf = g_colflag[br] + b * HW;
#pragma unroll
        for (int i = 0; i < PER; i++) cf[base + i] = 0;
        if (br == 0) {
            unsigned char* sm = g_selmap + b * HW;
#pragma unroll
            for (int i = 0; i < PER; i++) sm[base + i] = 0;
        }
    }

    int c = 0;
#pragma unroll
    for (int i = 0; i < PER; i++) c += (fl[base + i] == 0);
    cnt[t] = c;
    __syncthreads();
    for (int off = 1; off < 1024; off <<= 1) {
        int v = (t >= off) ? cnt[t - off] : 0;
        __syncthreads();
        cnt[t] += v;
        __syncthreads();
    }
    int pos = cnt[t] - c;
#pragma unroll
    for (int i = 0; i < PER; i++) {
        int j = base + i;
        if (fl[j] == 0) g_colidx[br][b][pos++] = j;
    }
}

// ---------------- kernel A3: B tile images + (fused) former row norms --------
// grid ((NTILES + 9), BATCH, 2):
//   blockIdx.x <  NTILES : build fragment-packed split B tile image
//   blockIdx.x >= NTILES : compute g_rn_f chunk (former-pixel inverse norms)
__global__ void bimage_kernel(const float* __restrict__ x,
                              const float* __restrict__ flip)
{
    __shared__ float raw[64][129];
    __shared__ float rcs[CTILE];
    const int t  = blockIdx.x;
    const int b  = blockIdx.y;
    const int br = blockIdx.z;
    const int tid = threadIdx.x;

    if (t >= NTILES) {
        // fused norms: chunk = (t-NTILES) + 9*br in [0,18), each block does 512 px
        int chunk = (t - NTILES) + 9 * br;
        const float* fx = x + (size_t)b * CHAN * HW;
#pragma unroll
        for (int i = 0; i < 2; i++) {
            int j = chunk * 512 + i * 256 + tid;
            float nf = 0.f;
#pragma unroll 8
            for (int c = 0; c < CF; c++) {
                float a = fx[(size_t)c * HW + j];
                nf += a * a;
            }
            g_rn_f[b * HW + j] = 1.0f / sqrtf(nf);
        }
        return;
    }

    const float* Bmat = br ? (flip + (size_t)b * CF * HW)
                           : (x + (size_t)b * CHAN * HW + (size_t)CF * HW);
    const int* cidx = g_colidx[br][b] + t * CTILE;

    for (int e = tid; e < CTILE * 64; e += 256) {
        int n = e & 127, k = e >> 7;
        raw[k][n] = Bmat[(size_t)k * HW + cidx[n]];
    }
    __syncthreads();

    if (tid < CTILE) {
        float s = 0.f;
#pragma unroll 8
        for (int k = 0; k < 64; k++) {
            float v = raw[k][tid];
            s += v * v;
        }
        rcs[tid] = 1.0f / sqrtf(s);
    }
    __syncthreads();

    float* dst_hi = &g_Bt[br][b][t][0][0];
    float* dst_lo = &g_Bt[br][b][t][1][0];
    for (int l = tid; l < TILE_PLANE; l += 256) {
        int np = l >> 10, ks = (l >> 7) & 7, ln = (l >> 2) & 31, e = l & 3;
        int tg = ln & 3, g = ln >> 2;
        int k = ks * 8 + tg + (e & 1) * 4;
        int n = np * 16 + (e >> 1) * 8 + g;
        float v  = raw[k][n] * rcs[n];
        float hi = tf32_rn(v);
        float lo = tf32_rn(v - hi);
        dst_hi[l] = hi;
        dst_lo[l] = lo;
    }
}

// ---------------- kernel B: scored argmax GEMM via mma.sync tf32 x3 ----------
// 512 thr = 16 warps; block tile 128r x 128c; warp tile 32r x 32c (grid 4x4).
// SINGLE barrier per tile: wait -> sync -> issue prefetch(t+1) -> compute.
// dyn smem: A_pk 64KB + B_pk[2 bufs] 128KB = 192KB
__global__ void __launch_bounds__(NTHREADS, 1)
score_kernel(const float* __restrict__ x,
             const int* __restrict__ p, const int* __restrict__ q)
{
    extern __shared__ __align__(16) char dyn[];
    __shared__ int   rowPix[RTILE];
    __shared__ float rnrow [RTILE];
    __shared__ float redv[RTILE * 16];
    __shared__ int   redj[RTILE * 16];

    const uint32_t sbase = smem_u32(dyn);
    const int rowBlk = blockIdx.x;
    const int b      = blockIdx.y;
    const int br     = blockIdx.z;
    const int tid  = threadIdx.x;
    const int lane = tid & 31;
    const int w    = tid >> 5;
    const int wr   = w & 3, wc = w >> 2;       // warp grid 4 (rows) x 4 (cols)
    const int tg   = lane & 3, g = lane >> 2;

    const int*   idx  = (br ? q : p) + b * MH;
    const float* Amat = x + (size_t)b * CHAN * HW;
    const int*   cidx = g_colidx[br][b];
    const float* Bsrc = &g_Bt[br][b][0][0][0];   // [tile][2][8192]

    if (tid < RTILE) {
        int pix = idx[rowBlk * RTILE + tid];
        rowPix[tid] = pix;
        rnrow [tid] = g_rn_f[b * HW + pix];
    }
    __syncthreads();

    // prologue: async-load B tile 0 (64KB) into buf 0
    {
        const float4* src = (const float4*)Bsrc;
#pragma unroll
        for (int i = 0; i < 8; i++) {
            int l = tid + i * NTHREADS;
            cp_async16(sbase + 65536u + l * 16, src + l);
        }
        cp_async_commit();
    }

    // A pack: gather rows, scale by row inverse norm, tf32 split, fragment layout
    // [plane][mt(8)][ks(8)][lane][4]: e0:(r,k) e1:(r+8,k) e2:(r,k+4) e3:(r+8,k+4)
    {
        float* Af = (float*)dyn;
        for (int l = tid; l < TILE_PLANE; l += NTHREADS) {
            int mt = l >> 10, ks = (l >> 7) & 7, ln = (l >> 2) & 31, e = l & 3;
            int ltg = ln & 3, lg = ln >> 2;
            int r = mt * 16 + lg + (e & 1) * 8;
            int k = ks * 8 + ltg + (e >> 1) * 4;
            float v  = Amat[(size_t)k * HW + rowPix[r]] * rnrow[r];
            float hi = tf32_rn(v);
            Af[l]              = hi;
            Af[TILE_PLANE + l] = tf32_rn(v - hi);
        }
    }

    float best[2][2];  int bestj[2][2];        // [mt][half(row +0/+8)], compact col
#pragma unroll
    for (int i = 0; i < 2; i++)
#pragma unroll
        for (int h = 0; h < 2; h++) { best[i][h] = __int_as_float(0xff800000); bestj[i][h] = 0; }

    const uint4* Apk = (const uint4*)dyn;         // plane stride 2048 uint4
    const int colbase = wc * 32 + tg * 2;         // tile-local compact col of e even

    for (int t = 0; t < NTILES; t++) {
        const int jt = t * CTILE;

        cp_async_wait0();
        __syncthreads();   // tile t visible to all; everyone done reading buf^1

        // prefetch t+1 into the other buffer (safe: barrier above ordered
        // all prior reads of buf^1 before these writes)
        if (t + 1 < NTILES) {
            const float4* src = (const float4*)(Bsrc + (size_t)(t + 1) * TILE_FLOATS);
            uint32_t dst = sbase + 65536u + ((t + 1) & 1) * 65536u;
#pragma unroll
            for (int i = 0; i < 8; i++) {
                int l = tid + i * NTHREADS;
                cp_async16(dst + l * 16, src + l);
            }
            cp_async_commit();
        }

        const uint4* Bpk = (const uint4*)(dyn + 65536 + (t & 1) * 65536);

        float acc[2][4][4];   // [mt][np*2+half][c0..c3]
#pragma unroll
        for (int mt = 0; mt < 2; mt++)
#pragma unroll
            for (int j = 0; j < 4; j++)
#pragma unroll
                for (int e = 0; e < 4; e++) acc[mt][j][e] = 0.f;

#pragma unroll 4
        for (int ks = 0; ks < 8; ks++) {
            uint4 ah[2], al[2], bh[2], bl[2];
#pragma unroll
            for (int mt = 0; mt < 2; mt++) {
                int o = ((wr * 2 + mt) * 8 + ks) * 32 + lane;
                ah[mt] = Apk[o];
                al[mt] = Apk[2048 + o];
            }
#pragma unroll
            for (int np = 0; np < 2; np++) {
                int o = ((wc * 2 + np) * 8 + ks) * 32 + lane;
                bh[np] = Bpk[o];
                bl[np] = Bpk[2048 + o];
            }
            // measured-good grouping: per (mt,np), 6 MMAs (a0 hh/hl/lh, a1 hh/hl/lh)
#pragma unroll
            for (int mt = 0; mt < 2; mt++) {
#pragma unroll
                for (int np = 0; np < 2; np++) {
                    float* a0 = acc[mt][np * 2];
                    float* a1 = acc[mt][np * 2 + 1];
                    mma8(a0, ah[mt], bh[np].x, bh[np].y);   // hi*hi
                    mma8(a0, ah[mt], bl[np].x, bl[np].y);   // hi*lo
                    mma8(a0, al[mt], bh[np].x, bh[np].y);   // lo*hi
                    mma8(a1, ah[mt], bh[np].z, bh[np].w);
                    mma8(a1, ah[mt], bl[np].z, bl[np].w);
                    mma8(a1, al[mt], bh[np].z, bh[np].w);
                }
            }
        }

        // epilogue: tree argmax in compact coords (strict-greater picks right
        // => lower column wins ties; columns ascend left-to-right everywhere)
#pragma unroll
        for (int mt = 0; mt < 2; mt++) {
#pragma unroll
            for (int h = 0; h < 2; h++) {
                float wv[4]; int wcid[4];
#pragma unroll
                for (int jj = 0; jj < 4; jj++) {
                    float v0 = acc[mt][jj][2 * h], v1 = acc[mt][jj][2 * h + 1];
                    bool gg = v1 > v0;
                    wv[jj]   = gg ? v1 : v0;
                    wcid[jj] = colbase + jj * 8 + (gg ? 1 : 0);
                }
                bool g0 = wv[1] > wv[0];
                float x0 = g0 ? wv[1] : wv[0];  int c0 = g0 ? wcid[1] : wcid[0];
                bool g1 = wv[3] > wv[2];
                float x1 = g1 ? wv[3] : wv[2];  int c1 = g1 ? wcid[3] : wcid[2];
                bool g2 = x1 > x0;
                float xt = g2 ? x1 : x0;        int ct = g2 ? c1 : c0;
                if (xt > best[mt][h]) { best[mt][h] = xt; bestj[mt][h] = jt + ct; }
            }
        }
        // no end-of-loop barrier: next iteration's wait+sync provides ordering
    }

    // final reduction: 16 slices per row; tie -> lower compact col (== lower orig col)
    const int slice = wc * 4 + tg;
#pragma unroll
    for (int mt = 0; mt < 2; mt++)
#pragma unroll
        for (int h = 0; h < 2; h++) {
            int r = wr * 32 + mt * 16 + g + h * 8;
            redv[r * 16 + slice] = best[mt][h];
            redj[r * 16 + slice] = bestj[mt][h];
        }
    __syncthreads();
    if (tid < RTILE) {
        float bv = __int_as_float(0xff800000);
        int bj = 0;
#pragma unroll 4
        for (int s = 0; s < 16; s++) {
            float v  = redv[tid * 16 + s];
            int   j2 = redj[tid * 16 + s];
            if (v > bv || (v == bv && j2 < bj)) { bv = v; bj = j2; }
        }
        int gi = b * MH + rowBlk * RTILE + tid;
        g_max[br][gi] = bv;
        g_arg[br][gi] = cidx[bj];      // compact -> original column index
    }
}

// ---------------- epilogue chain ---------------------------------------------
__global__ void scatter_kernel(const int* __restrict__ p)
{
    int t = blockIdx.x * 256 + threadIdx.x;
    if (t >= BATCH * MH) return;
    int b = t / MH;
    g_colflag[0][b * HW + g_arg[0][t]] = 1;
    g_colflag[1][b * HW + g_arg[1][t]] = 1;
    int pix = p[t];
    if (pix != 0)
        g_selmap[b * HW + pix] = (g_max[0][t] >= g_max[1][t]) ? 1 : 2;
}

__global__ void ssum_kernel(const float* __restrict__ x, const float* __restrict__ flip)
{
    int c  = blockIdx.x;
    int b  = blockIdx.y;
    int br = blockIdx.z;
    const float* Bmat = br ? (flip + (size_t)b * CF * HW)
                           : (x + (size_t)b * CHAN * HW + (size_t)CF * HW);
    const int* cfl = g_colflag[br] + b * HW;
    float s = 0.f;
    for (int j = threadIdx.x; j < HW; j += 256)
        if (cfl[j]) s += Bmat[(size_t)c * HW + j];
    __shared__ float red[256];
    red[threadIdx.x] = s;
    __syncthreads();
    for (int off = 128; off > 0; off >>= 1) {
        if (threadIdx.x < off) red[threadIdx.x] += red[threadIdx.x + off];
        __syncthreads();
    }
    if (threadIdx.x == 0) g_S[b][br][c] = red[0];
}

__global__ void out_kernel(const float* __restrict__ x, float* __restrict__ out)
{
    unsigned int idx = blockIdx.x * 256u + threadIdx.x;
    const unsigned int total = BATCH * 192u * HW;
    if (idx >= total) return;
    unsigned int b   = idx / (192u * HW);
    unsigned int rem = idx - b * 192u * HW;
    unsigned int ch  = rem / HW;
    unsigned int j   = rem - ch * HW;
    float v;
    if (ch < CHAN) {
        v = x[(size_t)b * CHAN * HW + rem];
    } else {
        int s = g_selmap[b * HW + j];
        v = s ? g_S[b][s - 1][ch - CHAN] : 0.f;
    }
    out[idx] = v;
}

// ---------------- launch -----------------------------------------------------
extern "C" void kernel_launch(void* const* d_in, const int* in_sizes, int n_in,
                              void* d_out, int out_size)
{
    const float* x     = (const float*)d_in[0];
    const float* flip  = (const float*)d_in[1];
    const int*   flag  = (const int*)d_in[2];
    const int*   flagf = (const int*)d_in[3];
    const int*   p     = (const int*)d_in[4];
    const int*   q     = (const int*)d_in[5];
    float* out = (float*)d_out;

    const int score_smem = 65536 + 2 * 65536;       // A_pk + 2 B buffers = 192 KB
    static bool attr_set = false;
    if (!attr_set) {
        cudaFuncSetAttribute(score_kernel,
                             cudaFuncAttributeMaxDynamicSharedMemorySize, score_smem);
        attr_set = true;
    }

    compact_kernel <<<dim3(BATCH, 2), 1024>>>(flag, flagf);
    bimage_kernel  <<<dim3(NTILES + 9, BATCH, 2), 256>>>(x, flip);
    score_kernel   <<<dim3(NROWB, BATCH, 2), NTHREADS, score_smem>>>(x, p, q);
    scatter_kernel <<<(BATCH * MH + 255) / 256, 256>>>(p);
    ssum_kernel    <<<dim3(CF, BATCH, 2), 256>>>(x, flip);
    out_kernel     <<<(BATCH * 192 * HW + 255) / 256, 256>>>(x, out);
}